// round 11
// baseline (speedup 1.0000x reference)
#include <cuda_runtime.h>
#include <cstdint>

#define B_    32
#define IC_   16
#define OC_   16
#define KTOT  65536      // (M-1)*(N-1)
#define E_    131584     // edges
#define VOFF  65792      // M*(N-1)
#define KT    32         // k per tile
#define NBUF  4          // weight pipeline depth
#define SLABB 8192       // slab bytes: 16 o x 32 k x 16B
#define NTILE (KTOT / KT)   // 2048

__device__ __forceinline__ unsigned long long pack2(float lo, float hi) {
    unsigned long long r;
    asm("mov.b64 %0, {%1, %2};" : "=l"(r) : "f"(lo), "f"(hi));
    return r;
}
__device__ __forceinline__ void fma2(unsigned long long &acc,
                                     unsigned long long a, unsigned long long b) {
    asm("fma.rn.f32x2 %0, %1, %2, %0;" : "+l"(acc) : "l"(a), "l"(b));
}
__device__ __forceinline__ float2 unpack2(unsigned long long v) {
    float2 f;
    asm("mov.b64 {%0, %1}, %2;" : "=f"(f.x), "=f"(f.y) : "l"(v));
    return f;
}
__device__ __forceinline__ void mbar_init(unsigned a, unsigned cnt) {
    asm volatile("mbarrier.init.shared.b64 [%0], %1;" :: "r"(a), "r"(cnt) : "memory");
}
__device__ __forceinline__ void mbar_arrive(unsigned a) {
    asm volatile("mbarrier.arrive.shared.b64 _, [%0];" :: "r"(a) : "memory");
}
__device__ __forceinline__ void mbar_expect_tx(unsigned a, unsigned bytes) {
    asm volatile("mbarrier.arrive.expect_tx.shared.b64 _, [%0], %1;"
                 :: "r"(a), "r"(bytes) : "memory");
}
__device__ __forceinline__ void mbar_wait(unsigned a, unsigned phase) {
    asm volatile(
        "{\n\t"
        ".reg .pred P;\n"
        "WAIT_%=:\n\t"
        "mbarrier.try_wait.parity.acquire.cta.shared::cta.b64 P, [%0], %1, 0x989680;\n\t"
        "@P bra.uni DONE_%=;\n\t"
        "bra.uni WAIT_%=;\n"
        "DONE_%=:\n\t"
        "}"
        :: "r"(a), "r"(phase) : "memory");
}
__device__ __forceinline__ void bulk_cp512(unsigned dst, const char* src, unsigned mbar) {
    asm volatile(
        "cp.async.bulk.shared::cluster.global.mbarrier::complete_tx::bytes "
        "[%0], [%1], 512, [%2];"
        :: "r"(dst), "l"(src), "r"(mbar) : "memory");
}

// Persistent CTAs: 148 blocks x 512 threads, each walks ~14 k-tiles.
// Weight slabs (8KB: 16 o x 32 k x float4) flow through a 4-deep
// mbarrier-tracked bulk-copy pipeline: tid0 produces, all 16 warps consume,
// one lane per warp arrives on empty. NO CTA barrier in the steady state ->
// warps skew freely up to 3 stages.
__global__ __launch_bounds__(512, 1)
void edges_kernel(const float* __restrict__ x,
                  const float4* __restrict__ w4,
                  const float* __restrict__ bias,
                  float* __restrict__ out)
{
    __shared__ __align__(1024) float4 sw[NBUF][16 * KT];
    __shared__ __align__(8) unsigned long long mbars[2 * NBUF]; // full[0..3], empty[0..3]

    const int lane = threadIdx.x;
    const int y    = threadIdx.y;
    const int oh   = y >> 3;
    const int bg   = y & 7;
    const int bbase = bg * 4;
    const int gstride = gridDim.x;
    const bool prod = (threadIdx.x == 0 && threadIdx.y == 0);

    const unsigned sw_base  = (unsigned)__cvta_generic_to_shared(&sw[0][0]);
    const unsigned mb_full  = (unsigned)__cvta_generic_to_shared(&mbars[0]);
    const unsigned mb_empty = mb_full + 8 * NBUF;
    const char* wb = (const char*)w4;

    const int tile0  = blockIdx.x;
    const int ntiles = (NTILE - tile0 + gstride - 1) / gstride;
    const int mtot   = ntiles * IC_;

    if (prod) {
        #pragma unroll
        for (int s = 0; s < NBUF; ++s) {
            mbar_init(mb_full + 8 * s, 1);     // expect_tx arrive
            mbar_init(mb_empty + 8 * s, 16);   // one arrive per warp
        }
    }
    __syncthreads();   // the only CTA-wide barrier

    // ---- producer prologue: stages 0..2 ----
    if (prod) {
        #pragma unroll
        for (int s = 0; s < 3; ++s) {
            const int buf = s & (NBUF - 1);
            mbar_expect_tx(mb_full + 8 * buf, SLABB);
            const char* src = wb
                + ((size_t)(s & 15) * KTOT + (size_t)(tile0 + (s >> 4) * gstride) * KT) * 16;
            const unsigned dst = sw_base + buf * SLABB;
            #pragma unroll
            for (int o = 0; o < 16; ++o)
                bulk_cp512(dst + o * 512, src + (size_t)o * ((size_t)IC_ * KTOT * 16),
                           mb_full + 8 * buf);
        }
    }

    // ---- consumer state ----
    const float* xp[4];
    #pragma unroll
    for (int bb = 0; bb < 4; ++bb)
        xp[bb] = x + (size_t)((bbase + bb) * IC_) * E_;

    float bo[8];
    #pragma unroll
    for (int oo = 0; oo < 8; ++oo) bo[oo] = __ldg(&bias[oh * 8 + oo]);

    int k0 = tile0 * KT;
    int k  = k0 + lane;
    int c0 = k;
    int c2 = VOFF + (k0 >> 8) * 257 + (k0 & 255) + lane;

    float xf[4][4];
    #pragma unroll
    for (int bb = 0; bb < 4; ++bb) {
        const float* xb = xp[bb];
        xf[bb][0] = __ldg(xb + c0);
        xf[bb][1] = __ldg(xb + c0 + 256);
        xf[bb][2] = __ldg(xb + c2);
        xf[bb][3] = __ldg(xb + c2 + 1);
    }

    int m = 0;
    for (int t = 0; t < ntiles; ++t) {
        unsigned long long acc[8][4];
        #pragma unroll
        for (int oo = 0; oo < 8; ++oo)
            #pragma unroll
            for (int bb = 0; bb < 4; ++bb) acc[oo][bb] = 0ull;

        #pragma unroll 1
        for (int ic = 0; ic < IC_; ++ic, ++m) {
            const int buf = m & (NBUF - 1);

            // wait for slab m (acquire)
            mbar_wait(mb_full + 8 * buf, (m >> 2) & 1);

            // producer: launch stage m+3 (buffer freed by stage m-1 consumers)
            if (prod && (m + 3 < mtot)) {
                const int s   = m + 3;
                const int nb  = s & (NBUF - 1);
                mbar_wait(mb_empty + 8 * nb, ((s >> 2) + 1) & 1);
                mbar_expect_tx(mb_full + 8 * nb, SLABB);
                const char* src = wb
                    + ((size_t)(s & 15) * KTOT
                       + (size_t)(tile0 + (s >> 4) * gstride) * KT) * 16;
                const unsigned dst = sw_base + nb * SLABB;
                #pragma unroll
                for (int o = 0; o < 16; ++o)
                    bulk_cp512(dst + o * 512,
                               src + (size_t)o * ((size_t)IC_ * KTOT * 16),
                               mb_full + 8 * nb);
            }

            // pack current x
            unsigned long long xA[4], xB[4];
            #pragma unroll
            for (int bb = 0; bb < 4; ++bb) {
                xA[bb] = pack2(xf[bb][0], xf[bb][1]);
                xB[bb] = pack2(xf[bb][2], xf[bb][3]);
            }

            // prefetch x for next stage
            if (ic < IC_ - 1) {
                const int off = (ic + 1) * E_;
                #pragma unroll
                for (int bb = 0; bb < 4; ++bb) {
                    const float* xb = xp[bb] + off;
                    xf[bb][0] = __ldg(xb + c0);
                    xf[bb][1] = __ldg(xb + c0 + 256);
                    xf[bb][2] = __ldg(xb + c2);
                    xf[bb][3] = __ldg(xb + c2 + 1);
                }
            } else if (t + 1 < ntiles) {
                const int k0n = k0 + gstride * KT;
                const int c0n = k0n + lane;
                const int c2n = VOFF + (k0n >> 8) * 257 + (k0n & 255) + lane;
                #pragma unroll
                for (int bb = 0; bb < 4; ++bb) {
                    const float* xb = xp[bb];
                    xf[bb][0] = __ldg(xb + c0n);
                    xf[bb][1] = __ldg(xb + c0n + 256);
                    xf[bb][2] = __ldg(xb + c2n);
                    xf[bb][3] = __ldg(xb + c2n + 1);
                }
            }

            // compute: 8 o x 4 b x 2 fma2
            const unsigned sa = sw_base + buf * SLABB + ((oh * 8) * KT + lane) * 16;
            #pragma unroll
            for (int oo = 0; oo < 8; ++oo) {
                unsigned long long wA, wB;
                asm("ld.shared.v2.u64 {%0, %1}, [%2];"
                    : "=l"(wA), "=l"(wB) : "r"(sa + oo * (KT * 16)));
                #pragma unroll
                for (int bb = 0; bb < 4; ++bb) {
                    fma2(acc[oo][bb], wA, xA[bb]);
                    fma2(acc[oo][bb], wB, xB[bb]);
                }
            }

            // release buffer (one arrive per warp; release orders prior LDS)
            if (lane == 0) mbar_arrive(mb_empty + 8 * buf);
        }

        // epilogue for this tile
        #pragma unroll
        for (int oo = 0; oo < 8; ++oo) {
            const int o = oh * 8 + oo;
            #pragma unroll
            for (int bb = 0; bb < 4; ++bb) {
                float2 v = unpack2(acc[oo][bb]);
                out[(size_t)((bbase + bb) * OC_ + o) * KTOT + k] = v.x + v.y + bo[oo];
            }
        }

        k0 += gstride * KT;
        k   = k0 + lane;
        c0  = k;
        c2  = VOFF + (k0 >> 8) * 257 + (k0 & 255) + lane;
    }
}

extern "C" void kernel_launch(void* const* d_in, const int* in_sizes, int n_in,
                              void* d_out, int out_size)
{
    const float*  x    = (const float*)d_in[0];
    const float4* w4   = (const float4*)d_in[1];
    const float*  bias = (const float*)d_in[2];
    float*        out  = (float*)d_out;

    dim3 block(32, 16);
    dim3 grid(148);
    edges_kernel<<<grid, block>>>(x, w4, bias, out);
}